// round 6
// baseline (speedup 1.0000x reference)
#include <cuda_runtime.h>
#include <math.h>

#define NB 8
#define NC 19
#define HW (512 * 512)
#define TPX 256                   // pixels per pipeline stage
#define NTILES (HW / TPX)         // 1024
#define SMOOTH 1e-08f
#define GRID_X 38
#define NBLOCKS (GRID_X * NB)
#define NTHREADS 256
#define STAGE_BYTES ((NC + 1) * TPX * 4)   // 19 classes + target = 20480 B

__device__ float g_acc[2 * NB * NC];   // [0..152)=tp, [152..304)=den
__device__ unsigned int g_done = 0;

__device__ __forceinline__ unsigned int smem_u32(const void* p) {
    unsigned int a;
    asm("{ .reg .u64 t; cvta.to.shared.u64 t, %1; cvt.u32.u64 %0, t; }"
        : "=r"(a) : "l"(p));
    return a;
}
__device__ __forceinline__ void mbar_init(unsigned int mbar, unsigned int cnt) {
    asm volatile("mbarrier.init.shared.b64 [%0], %1;" :: "r"(mbar), "r"(cnt) : "memory");
}
__device__ __forceinline__ void mbar_expect_tx(unsigned int mbar, unsigned int bytes) {
    asm volatile("mbarrier.arrive.expect_tx.shared.b64 _, [%0], %1;"
                 :: "r"(mbar), "r"(bytes) : "memory");
}
__device__ __forceinline__ void mbar_wait(unsigned int mbar, unsigned int parity) {
    asm volatile(
        "{\n\t.reg .pred P;\n\t"
        "WAIT_%=:\n\t"
        "mbarrier.try_wait.parity.shared.b64 P, [%0], %1;\n\t"
        "@!P bra.uni WAIT_%=;\n\t}"
        :: "r"(mbar), "r"(parity) : "memory");
}
__device__ __forceinline__ void bulk_g2s(unsigned int dst_s, const void* src_g,
                                         unsigned int bytes, unsigned int mbar) {
    asm volatile(
        "cp.async.bulk.shared::cta.global.mbarrier::complete_tx::bytes "
        "[%0], [%1], %2, [%3];"
        :: "r"(dst_s), "l"(src_g), "r"(bytes), "r"(mbar) : "memory");
}
__device__ __forceinline__ float ex2f(float x) {
    asm("ex2.approx.f32 %0, %0;" : "+f"(x));
    return x;
}

__global__ __launch_bounds__(NTHREADS, 2) void tversky_fused_kernel(
    const float* __restrict__ pred, const int* __restrict__ target,
    float* __restrict__ out) {
    const int b = blockIdx.y;
    const int bx = blockIdx.x;
    const float* __restrict__ ps_g = pred + (size_t)b * NC * HW;
    const int* __restrict__ tg_g = target + (size_t)b * HW;
    const int tid = threadIdx.x;

    __shared__ __align__(16) float s_pred[2][NC][TPX];
    __shared__ __align__(16) int s_tgt[2][TPX];
    __shared__ __align__(8) unsigned long long s_mbar[2];
    __shared__ float s_acc[2 * NC];
    __shared__ float s_red[NTHREADS];
    __shared__ int s_is_last;

    const unsigned int mb0 = smem_u32(&s_mbar[0]);
    const unsigned int mb1 = smem_u32(&s_mbar[1]);

    if (tid == 0) { mbar_init(mb0, 1); mbar_init(mb1, 1); }
    if (tid < 2 * NC) s_acc[tid] = 0.0f;
    __syncthreads();

    // prologue: issue the first two stages
    if (tid == 0) {
#pragma unroll 1
        for (int st = 0; st < 2; st++) {
            const int t = bx + st * GRID_X;   // always < NTILES (bx < 38)
            const unsigned int mb = st ? mb1 : mb0;
            mbar_expect_tx(mb, STAGE_BYTES);
#pragma unroll
            for (int c = 0; c < NC; c++)
                bulk_g2s(smem_u32(&s_pred[st][c][0]),
                         ps_g + (size_t)c * HW + (size_t)t * TPX, TPX * 4, mb);
            bulk_g2s(smem_u32(&s_tgt[st][0]), tg_g + (size_t)t * TPX, TPX * 4, mb);
        }
    }

    float rtp[NC], rden[NC];
#pragma unroll
    for (int c = 0; c < NC; c++) { rtp[c] = 0.0f; rden[c] = 0.0f; }

    const float LOG2E = 1.4426950408889634f;
    int phase0 = 0, phase1 = 0;
    int s = 0;
    for (int t = bx; t < NTILES; t += GRID_X, s ^= 1) {
        if (s == 0) { mbar_wait(mb0, phase0); phase0 ^= 1; }
        else        { mbar_wait(mb1, phase1); phase1 ^= 1; }

        float e[NC];
#pragma unroll
        for (int c = 0; c < NC; c++) e[c] = s_pred[s][c][tid];
        const int tg = s_tgt[s][tid];

        float sum = 0.0f;
#pragma unroll
        for (int c = 0; c < NC; c++) { e[c] = ex2f(e[c] * LOG2E); sum += e[c]; }
        const float r = __fdividef(1.0f, sum);

#pragma unroll
        for (int c = 0; c < NC; c++) {
            const float p = e[c] * r;
            rden[c] += p;
            if (tg == c) { rtp[c] += p; rden[c] += 1.0f; }
        }

        __syncthreads();   // everyone done reading buffer s
        const int tn = t + 2 * GRID_X;
        if (tid == 0 && tn < NTILES) {
            const unsigned int mb = s ? mb1 : mb0;
            mbar_expect_tx(mb, STAGE_BYTES);
#pragma unroll
            for (int c = 0; c < NC; c++)
                bulk_g2s(smem_u32(&s_pred[s][c][0]),
                         ps_g + (size_t)c * HW + (size_t)tn * TPX, TPX * 4, mb);
            bulk_g2s(smem_u32(&s_tgt[s][0]), tg_g + (size_t)tn * TPX, TPX * 4, mb);
        }
    }

    // warp-level reduction of the 38 accumulators
#pragma unroll
    for (int c = 0; c < NC; c++) {
#pragma unroll
        for (int off = 16; off > 0; off >>= 1) {
            rtp[c]  += __shfl_down_sync(0xFFFFFFFFu, rtp[c],  off);
            rden[c] += __shfl_down_sync(0xFFFFFFFFu, rden[c], off);
        }
    }
    if ((tid & 31) == 0) {
#pragma unroll
        for (int c = 0; c < NC; c++) {
            atomicAdd(&s_acc[c], rtp[c]);
            atomicAdd(&s_acc[NC + c], rden[c]);
        }
    }
    __syncthreads();

    if (tid < 2 * NC) {
        const int sec = tid / NC;
        const int c = tid - sec * NC;
        atomicAdd(&g_acc[sec * NB * NC + b * NC + c], s_acc[tid]);
    }

    // last-block-done epilogue
    __threadfence();
    if (tid == 0) {
        unsigned int n = atomicAdd(&g_done, 1u);
        s_is_last = (n == NBLOCKS - 1);
    }
    __syncthreads();
    if (!s_is_last) return;

    float v = 0.0f;
    if (tid < NB * NC) {
        const float tp = __ldcg(&g_acc[tid]);
        const float dn = __ldcg(&g_acc[NB * NC + tid]);
        v = 1.0f - (tp + SMOOTH) / (0.5f * dn + SMOOTH);  // alpha=beta=0.5
    }
    s_red[tid] = v;
    __syncthreads();
#pragma unroll
    for (int off = NTHREADS / 2; off > 0; off >>= 1) {
        if (tid < off) s_red[tid] += s_red[tid + off];
        __syncthreads();
    }
    if (tid == 0) {
        out[0] = s_red[0] / (float)(NB * NC);
        g_done = 0u;
    }
    for (int i = tid; i < 2 * NB * NC; i += NTHREADS) g_acc[i] = 0.0f;
}

extern "C" void kernel_launch(void* const* d_in, const int* in_sizes, int n_in,
                              void* d_out, int out_size) {
    const float* pred = (const float*)d_in[0];
    const int* target = (const int*)d_in[1];
    float* out = (float*)d_out;

    dim3 grid(GRID_X, NB);
    tversky_fused_kernel<<<grid, NTHREADS>>>(pred, target, out);
}

// round 7
// speedup vs baseline: 1.1164x; 1.1164x over previous
#include <cuda_runtime.h>
#include <math.h>

#define NB 8
#define NC 19
#define HW (512 * 512)
#define HW2 (HW / 2)
#define SMOOTH 1e-08f
#define GRID_X 56
#define NBLOCKS (GRID_X * NB)
#define NTHREADS 256

__device__ float g_acc[2 * NB * NC];   // [0..152)=tp, [152..304)=den
__device__ unsigned int g_done = 0;

__device__ __forceinline__ float ex2f(float x) {
    asm("ex2.approx.f32 %0, %0;" : "+f"(x));
    return x;
}

__global__ __launch_bounds__(NTHREADS, 3) void tversky_fused_kernel(
    const float* __restrict__ pred, const int* __restrict__ target,
    float* __restrict__ out) {
    const int b = blockIdx.y;
    const float2* __restrict__ p2 =
        (const float2*)(pred + (size_t)b * NC * HW);
    const int2* __restrict__ t2 = (const int2*)(target + (size_t)b * HW);
    const int tid = threadIdx.x;

    __shared__ float s_tp[NC];
    __shared__ float s_den[NC];
    __shared__ int s_is_last;
    if (tid < NC) { s_tp[tid] = 0.0f; s_den[tid] = 0.0f; }
    __syncthreads();

    float rden[NC];
#pragma unroll
    for (int c = 0; c < NC; c++) rden[c] = 0.0f;

    const float LOG2E = 1.4426950408889634f;
    const int stride = GRID_X * NTHREADS;
    for (int idx = blockIdx.x * NTHREADS + tid; idx < HW2; idx += stride) {
        float2 e[NC];
#pragma unroll
        for (int c = 0; c < NC; c++) e[c] = __ldcs(&p2[(size_t)c * HW2 + idx]);
        const int2 tg = t2[idx];

        float sx = 0.0f, sy = 0.0f;
#pragma unroll
        for (int c = 0; c < NC; c++) {
            e[c].x = ex2f(e[c].x * LOG2E);
            e[c].y = ex2f(e[c].y * LOG2E);
            sx += e[c].x;
            sy += e[c].y;
        }
        const float rx = __fdividef(1.0f, sx);
        const float ry = __fdividef(1.0f, sy);

        // select e at the target class (ALU-pipe FSEL chain, no extra regs/class)
        float etx = 0.0f, ety = 0.0f;
#pragma unroll
        for (int c = 0; c < NC; c++) {
            if (tg.x == c) etx = e[c].x;
            if (tg.y == c) ety = e[c].y;
        }

#pragma unroll
        for (int c = 0; c < NC; c++) {
            rden[c] = fmaf(e[c].x, rx, rden[c]);
            rden[c] = fmaf(e[c].y, ry, rden[c]);
            if (tg.x == c) rden[c] += 1.0f;
            if (tg.y == c) rden[c] += 1.0f;
        }

        atomicAdd(&s_tp[tg.x], etx * rx);
        atomicAdd(&s_tp[tg.y], ety * ry);
    }

    // warp-level reduction of the 19 den accumulators
#pragma unroll
    for (int c = 0; c < NC; c++) {
#pragma unroll
        for (int off = 16; off > 0; off >>= 1)
            rden[c] += __shfl_down_sync(0xFFFFFFFFu, rden[c], off);
    }
    if ((tid & 31) == 0) {
#pragma unroll
        for (int c = 0; c < NC; c++) atomicAdd(&s_den[c], rden[c]);
    }
    __syncthreads();

    // block -> global (38 atomics from first 38 threads)
    if (tid < 2 * NC) {
        const int sec = tid / NC;
        const int c = tid - sec * NC;
        const float v = (sec == 0) ? s_tp[c] : s_den[c];
        atomicAdd(&g_acc[sec * NB * NC + b * NC + c], v);
    }

    // last-block-done epilogue
    __threadfence();
    if (tid == 0) {
        unsigned int n = atomicAdd(&g_done, 1u);
        s_is_last = (n == NBLOCKS - 1);
    }
    __syncthreads();
    if (!s_is_last) return;

    __shared__ float s_red[NTHREADS];
    float v = 0.0f;
    if (tid < NB * NC) {
        const float tp = __ldcg(&g_acc[tid]);
        const float dn = __ldcg(&g_acc[NB * NC + tid]);
        v = 1.0f - (tp + SMOOTH) / (0.5f * dn + SMOOTH);  // alpha=beta=0.5
    }
    s_red[tid] = v;
    __syncthreads();
#pragma unroll
    for (int off = NTHREADS / 2; off > 0; off >>= 1) {
        if (tid < off) s_red[tid] += s_red[tid + off];
        __syncthreads();
    }
    if (tid == 0) {
        out[0] = s_red[0] / (float)(NB * NC);
        g_done = 0u;
    }
    for (int i = tid; i < 2 * NB * NC; i += NTHREADS) g_acc[i] = 0.0f;
}

extern "C" void kernel_launch(void* const* d_in, const int* in_sizes, int n_in,
                              void* d_out, int out_size) {
    const float* pred = (const float*)d_in[0];
    const int* target = (const int*)d_in[1];
    float* out = (float*)d_out;

    dim3 grid(GRID_X, NB);
    tversky_fused_kernel<<<grid, NTHREADS>>>(pred, target, out);
}

// round 8
// speedup vs baseline: 1.1801x; 1.0570x over previous
#include <cuda_runtime.h>
#include <math.h>

#define NB 8
#define NC 19
#define HW (512 * 512)
#define HW2 (HW / 2)
#define SMOOTH 1e-08f
#define NTHREADS 128
#define GRID_X 74                       // 74*8 = 592 = 4 CTAs * 148 SMs
#define NBLOCKS (GRID_X * NB)

__device__ float g_acc[2 * NB * NC];    // [0..152)=tp, [152..304)=den
__device__ unsigned int g_done = 0;

__device__ __forceinline__ unsigned int smem_u32(const void* p) {
    unsigned int a;
    asm("{ .reg .u64 t; cvta.to.shared.u64 t, %1; cvt.u32.u64 %0, t; }"
        : "=r"(a) : "l"(p));
    return a;
}
__device__ __forceinline__ void cp8(void* dst_s, const void* src_g) {
    asm volatile("cp.async.ca.shared.global [%0], [%1], 8;"
                 :: "r"(smem_u32(dst_s)), "l"(src_g) : "memory");
}
__device__ __forceinline__ void cp_commit() {
    asm volatile("cp.async.commit_group;" ::: "memory");
}
__device__ __forceinline__ void cp_wait1() {
    asm volatile("cp.async.wait_group 1;" ::: "memory");
}
__device__ __forceinline__ float ex2f(float x) {
    asm("ex2.approx.f32 %0, %0;" : "+f"(x));
    return x;
}

__global__ __launch_bounds__(NTHREADS, 4) void tversky_fused_kernel(
    const float* __restrict__ pred, const int* __restrict__ target,
    float* __restrict__ out) {
    const int b = blockIdx.y;
    const float2* __restrict__ p2 =
        (const float2*)(pred + (size_t)b * NC * HW);
    const int2* __restrict__ t2 = (const int2*)(target + (size_t)b * HW);
    const int tid = threadIdx.x;

    // per-thread-slot staging: thread t only ever touches [..][..][t]
    __shared__ __align__(16) float2 s_e[2][NC][NTHREADS];   // 38912 B
    __shared__ __align__(16) int2 s_t[2][NTHREADS];         //  2048 B
    __shared__ float s_acc[2 * NC];
    __shared__ float s_red[NTHREADS];
    __shared__ int s_is_last;

    if (tid < 2 * NC) s_acc[tid] = 0.0f;
    __syncthreads();

    const int stride = GRID_X * NTHREADS;
    const int idx0 = blockIdx.x * NTHREADS + tid;

    // prologue: issue stages 0 and 1 (per-thread, guarded, always committed)
#pragma unroll
    for (int st = 0; st < 2; st++) {
        const int idx = idx0 + st * stride;
        if (idx < HW2) {
#pragma unroll
            for (int c = 0; c < NC; c++)
                cp8(&s_e[st][c][tid], &p2[(size_t)c * HW2 + idx]);
            cp8(&s_t[st][tid], &t2[idx]);
        }
        cp_commit();
    }

    float rtp[NC], rden[NC];
#pragma unroll
    for (int c = 0; c < NC; c++) { rtp[c] = 0.0f; rden[c] = 0.0f; }

    const float LOG2E = 1.4426950408889634f;
    int s = 0;
    for (int idx = idx0; idx < HW2; idx += stride, s ^= 1) {
        cp_wait1();   // this thread's stage s is resident

        float2 e[NC];
#pragma unroll
        for (int c = 0; c < NC; c++) e[c] = s_e[s][c][tid];
        const int2 tg = s_t[s][tid];

        // refill buffer s for stage idx+2*stride (no sync needed: own slots)
        const int tn = idx + 2 * stride;
        if (tn < HW2) {
#pragma unroll
            for (int c = 0; c < NC; c++)
                cp8(&s_e[s][c][tid], &p2[(size_t)c * HW2 + tn]);
            cp8(&s_t[s][tid], &t2[tn]);
        }
        cp_commit();

        float sx = 0.0f, sy = 0.0f;
#pragma unroll
        for (int c = 0; c < NC; c++) {
            e[c].x = ex2f(e[c].x * LOG2E);
            e[c].y = ex2f(e[c].y * LOG2E);
            sx += e[c].x;
            sy += e[c].y;
        }
        const float rx = __fdividef(1.0f, sx);
        const float ry = __fdividef(1.0f, sy);

#pragma unroll
        for (int c = 0; c < NC; c++) {
            rden[c] = fmaf(e[c].x, rx, rden[c]);
            rden[c] = fmaf(e[c].y, ry, rden[c]);
            if (tg.x == c) { rtp[c] = fmaf(e[c].x, rx, rtp[c]); rden[c] += 1.0f; }
            if (tg.y == c) { rtp[c] = fmaf(e[c].y, ry, rtp[c]); rden[c] += 1.0f; }
        }
    }

    // warp-level reduction of the 38 accumulators
#pragma unroll
    for (int c = 0; c < NC; c++) {
#pragma unroll
        for (int off = 16; off > 0; off >>= 1) {
            rtp[c]  += __shfl_down_sync(0xFFFFFFFFu, rtp[c],  off);
            rden[c] += __shfl_down_sync(0xFFFFFFFFu, rden[c], off);
        }
    }
    if ((tid & 31) == 0) {
#pragma unroll
        for (int c = 0; c < NC; c++) {
            atomicAdd(&s_acc[c], rtp[c]);
            atomicAdd(&s_acc[NC + c], rden[c]);
        }
    }
    __syncthreads();

    if (tid < 2 * NC) {
        const int sec = tid / NC;
        const int c = tid - sec * NC;
        atomicAdd(&g_acc[sec * NB * NC + b * NC + c], s_acc[tid]);
    }

    // last-block-done epilogue
    __threadfence();
    if (tid == 0) {
        unsigned int n = atomicAdd(&g_done, 1u);
        s_is_last = (n == NBLOCKS - 1);
    }
    __syncthreads();
    if (!s_is_last) return;

    float v = 0.0f;
#pragma unroll
    for (int k = 0; k < 2; k++) {           // NB*NC=152 > 128 threads
        const int i = tid + k * NTHREADS;
        if (i < NB * NC) {
            const float tp = __ldcg(&g_acc[i]);
            const float dn = __ldcg(&g_acc[NB * NC + i]);
            v += 1.0f - (tp + SMOOTH) / (0.5f * dn + SMOOTH);  // alpha=beta=0.5
        }
    }
    s_red[tid] = v;
    __syncthreads();
#pragma unroll
    for (int off = NTHREADS / 2; off > 0; off >>= 1) {
        if (tid < off) s_red[tid] += s_red[tid + off];
        __syncthreads();
    }
    if (tid == 0) {
        out[0] = s_red[0] / (float)(NB * NC);
        g_done = 0u;
    }
    for (int i = tid; i < 2 * NB * NC; i += NTHREADS) g_acc[i] = 0.0f;
}

extern "C" void kernel_launch(void* const* d_in, const int* in_sizes, int n_in,
                              void* d_out, int out_size) {
    const float* pred = (const float*)d_in[0];
    const int* target = (const int*)d_in[1];
    float* out = (float*)d_out;

    dim3 grid(GRID_X, NB);
    tversky_fused_kernel<<<grid, NTHREADS>>>(pred, target, out);
}